// round 6
// baseline (speedup 1.0000x reference)
#include <cuda_runtime.h>
#include <cuda_bf16.h>
#include <cstdint>

// Sinkhorn, 32 x 1024 x 1024, tau=1, 10 iterations — persistent kernel with
// FUSED iteration pairs. Each block owns a 128-row slab of one batch's E.
// A fused pass reads the slab ONCE: computes a_i = 1/(E_i,: . b) per row, then
// accumulates partial column sums sum_i a_i E_ij in registers -> block reduce
// -> per-block partials. After a per-batch barrier, every block redundantly
// combines the 8 blocks' partials into b (shared). 5 slab passes total
// instead of 9, 5 barriers instead of 10.

#define BATCH 32
#define N 1024
#define BPB 8                  // blocks per batch; grid = 8 x 32 = 256
#define TPB 512
#define WPB 16

__device__ __nv_bfloat16 g_E[(size_t)BATCH * N * N];   // 64 MB
__device__ float g_part[2][BPB][BATCH][N];             // 2 MB, double-buffered
__device__ float g_a[BATCH * N];
__device__ unsigned g_bar[BATCH * 32];

__global__ void k_zero_bar() { g_bar[threadIdx.x * 32] = 0u; }

__global__ void __launch_bounds__(TPB, 2) k_sinkhorn(const float* __restrict__ s,
                                                     float* __restrict__ out) {
    const int part = blockIdx.x;          // 0..7
    const int b    = blockIdx.y;          // 0..31
    const int w    = threadIdx.x >> 5;    // 0..15
    const int lane = threadIdx.x & 31;
    const size_t bN2 = (size_t)b * N * N;

    __shared__ float sh[N];               // b staging (4 KB)
    __shared__ float red[BPB][N];         // warp-partials reduce (32 KB)

    unsigned bar_target = 0;
    unsigned* const barp = &g_bar[b * 32];

    auto batch_barrier = [&]() {
        __threadfence();
        __syncthreads();
        bar_target += BPB;
        if (threadIdx.x == 0) {
            atomicAdd(barp, 1u);
            while (*(volatile unsigned*)barp < bar_target) { }
            __threadfence();
        }
        __syncthreads();
    };

    // acc[k*8+m] accumulates column (lane+32k)*8+m. Reduce 16 warps -> 8 in
    // shared, fold, write this block's 1024 partials to g_part[buf].
    auto block_reduce_store = [&](float* acc, int buf) {
        if (w < 8) {
            #pragma unroll
            for (int k = 0; k < 4; ++k) {
                const int j = (lane + 32 * k) * 8;
                *reinterpret_cast<float4*>(&red[w][j]) =
                    make_float4(acc[k*8+0], acc[k*8+1], acc[k*8+2], acc[k*8+3]);
                *reinterpret_cast<float4*>(&red[w][j+4]) =
                    make_float4(acc[k*8+4], acc[k*8+5], acc[k*8+6], acc[k*8+7]);
            }
        }
        __syncthreads();
        if (w >= 8) {
            #pragma unroll
            for (int k = 0; k < 4; ++k) {
                const int j = (lane + 32 * k) * 8;
                float4 r0 = *reinterpret_cast<float4*>(&red[w-8][j]);
                float4 r1 = *reinterpret_cast<float4*>(&red[w-8][j+4]);
                r0.x += acc[k*8+0]; r0.y += acc[k*8+1];
                r0.z += acc[k*8+2]; r0.w += acc[k*8+3];
                r1.x += acc[k*8+4]; r1.y += acc[k*8+5];
                r1.z += acc[k*8+6]; r1.w += acc[k*8+7];
                *reinterpret_cast<float4*>(&red[w-8][j])   = r0;
                *reinterpret_cast<float4*>(&red[w-8][j+4]) = r1;
            }
        }
        __syncthreads();
        {
            const int c = threadIdx.x * 2;
            float s0 = 0.f, s1 = 0.f;
            #pragma unroll
            for (int q = 0; q < 8; ++q) { s0 += red[q][c]; s1 += red[q][c+1]; }
            *reinterpret_cast<float2*>(&g_part[buf][part][b][c]) = make_float2(s0, s1);
        }
    };

    // Combine 8 blocks' partials (other SMs wrote them -> bypass L1) -> b in sh.
    auto combine_b = [&](int buf) {
        const int c = threadIdx.x * 2;
        float s0 = 0.f, s1 = 0.f;
        #pragma unroll
        for (int q = 0; q < BPB; ++q) {
            float2 p = __ldcg(reinterpret_cast<const float2*>(&g_part[buf][q][b][c]));
            s0 += p.x; s1 += p.y;
        }
        sh[c]     = 1.0f / s0;
        sh[c + 1] = 1.0f / s1;
        __syncthreads();
    };

    // ============ phase 0 (iters 0+1): E=exp(s), a=1/rowsum, col partials ====
    float ai_arr[8];
    #pragma unroll 1
    for (int r8 = 0; r8 < 8; ++r8) {
        const int row = part * 128 + r8 * WPB + w;
        const size_t base = bN2 + (size_t)row * N;
        float sum = 0.f;
        #pragma unroll
        for (int k = 0; k < 4; ++k) {
            const int j = (lane + 32 * k) * 8;
            float4 s0 = *reinterpret_cast<const float4*>(s + base + j);
            float4 s1 = *reinterpret_cast<const float4*>(s + base + j + 4);
            float e0 = __expf(s0.x), e1 = __expf(s0.y), e2 = __expf(s0.z), e3 = __expf(s0.w);
            float e4 = __expf(s1.x), e5 = __expf(s1.y), e6 = __expf(s1.z), e7 = __expf(s1.w);
            __nv_bfloat162 p0 = __floats2bfloat162_rn(e0, e1);
            __nv_bfloat162 p1 = __floats2bfloat162_rn(e2, e3);
            __nv_bfloat162 p2 = __floats2bfloat162_rn(e4, e5);
            __nv_bfloat162 p3 = __floats2bfloat162_rn(e6, e7);
            uint4 packed;
            packed.x = *reinterpret_cast<uint32_t*>(&p0);
            packed.y = *reinterpret_cast<uint32_t*>(&p1);
            packed.z = *reinterpret_cast<uint32_t*>(&p2);
            packed.w = *reinterpret_cast<uint32_t*>(&p3);
            *reinterpret_cast<uint4*>(&g_E[base + j]) = packed;
            sum += ((e0 + e1) + (e2 + e3)) + ((e4 + e5) + (e6 + e7));
        }
        #pragma unroll
        for (int o = 16; o > 0; o >>= 1) sum += __shfl_xor_sync(0xFFFFFFFFu, sum, o);
        ai_arr[r8] = 1.0f / sum;
    }
    {
        float acc[32];
        #pragma unroll
        for (int k = 0; k < 32; ++k) acc[k] = 0.f;
        #pragma unroll 1
        for (int r8 = 0; r8 < 8; ++r8) {
            const int row = part * 128 + r8 * WPB + w;
            const size_t base = bN2 + (size_t)row * N;
            const float ai = ai_arr[r8];
            #pragma unroll
            for (int k = 0; k < 4; ++k) {
                const int j = (lane + 32 * k) * 8;
                uint4 u = *reinterpret_cast<const uint4*>(&g_E[base + j]);
                float2 f0 = __bfloat1622float2(*reinterpret_cast<__nv_bfloat162*>(&u.x));
                float2 f1 = __bfloat1622float2(*reinterpret_cast<__nv_bfloat162*>(&u.y));
                float2 f2 = __bfloat1622float2(*reinterpret_cast<__nv_bfloat162*>(&u.z));
                float2 f3 = __bfloat1622float2(*reinterpret_cast<__nv_bfloat162*>(&u.w));
                acc[k*8+0] = fmaf(ai, f0.x, acc[k*8+0]);
                acc[k*8+1] = fmaf(ai, f0.y, acc[k*8+1]);
                acc[k*8+2] = fmaf(ai, f1.x, acc[k*8+2]);
                acc[k*8+3] = fmaf(ai, f1.y, acc[k*8+3]);
                acc[k*8+4] = fmaf(ai, f2.x, acc[k*8+4]);
                acc[k*8+5] = fmaf(ai, f2.y, acc[k*8+5]);
                acc[k*8+6] = fmaf(ai, f3.x, acc[k*8+6]);
                acc[k*8+7] = fmaf(ai, f3.y, acc[k*8+7]);
            }
        }
        block_reduce_store(acc, 0);
    }
    batch_barrier();

    // ============ fused passes p=1..4 (iters 2+3, 4+5, 6+7, 8+9) ============
    #pragma unroll 1
    for (int p = 1; p <= 4; ++p) {
        combine_b((p - 1) & 1);           // finish previous col update -> b in sh
        const bool store_a = (p == 4);

        float acc[32];
        #pragma unroll
        for (int k = 0; k < 32; ++k) acc[k] = 0.f;

        #pragma unroll 1
        for (int r8 = 0; r8 < 8; ++r8) {
            const int row = part * 128 + r8 * WPB + w;
            const size_t base = bN2 + (size_t)row * N;
            uint4 u[4];
            #pragma unroll
            for (int k = 0; k < 4; ++k)
                u[k] = *reinterpret_cast<const uint4*>(&g_E[base + (lane + 32 * k) * 8]);

            float sum = 0.f;
            #pragma unroll
            for (int k = 0; k < 4; ++k) {
                const int j = (lane + 32 * k) * 8;
                float4 b0 = *reinterpret_cast<const float4*>(&sh[j]);
                float4 b1 = *reinterpret_cast<const float4*>(&sh[j + 4]);
                float2 f0 = __bfloat1622float2(*reinterpret_cast<__nv_bfloat162*>(&u[k].x));
                float2 f1 = __bfloat1622float2(*reinterpret_cast<__nv_bfloat162*>(&u[k].y));
                float2 f2 = __bfloat1622float2(*reinterpret_cast<__nv_bfloat162*>(&u[k].z));
                float2 f3 = __bfloat1622float2(*reinterpret_cast<__nv_bfloat162*>(&u[k].w));
                sum = fmaf(f0.x, b0.x, sum); sum = fmaf(f0.y, b0.y, sum);
                sum = fmaf(f1.x, b0.z, sum); sum = fmaf(f1.y, b0.w, sum);
                sum = fmaf(f2.x, b1.x, sum); sum = fmaf(f2.y, b1.y, sum);
                sum = fmaf(f3.x, b1.z, sum); sum = fmaf(f3.y, b1.w, sum);
            }
            #pragma unroll
            for (int o = 16; o > 0; o >>= 1) sum += __shfl_xor_sync(0xFFFFFFFFu, sum, o);
            const float ai = 1.0f / sum;
            if (store_a && lane == 0) g_a[b * N + row] = ai;

            #pragma unroll
            for (int k = 0; k < 4; ++k) {
                float2 f0 = __bfloat1622float2(*reinterpret_cast<__nv_bfloat162*>(&u[k].x));
                float2 f1 = __bfloat1622float2(*reinterpret_cast<__nv_bfloat162*>(&u[k].y));
                float2 f2 = __bfloat1622float2(*reinterpret_cast<__nv_bfloat162*>(&u[k].z));
                float2 f3 = __bfloat1622float2(*reinterpret_cast<__nv_bfloat162*>(&u[k].w));
                acc[k*8+0] = fmaf(ai, f0.x, acc[k*8+0]);
                acc[k*8+1] = fmaf(ai, f0.y, acc[k*8+1]);
                acc[k*8+2] = fmaf(ai, f1.x, acc[k*8+2]);
                acc[k*8+3] = fmaf(ai, f1.y, acc[k*8+3]);
                acc[k*8+4] = fmaf(ai, f2.x, acc[k*8+4]);
                acc[k*8+5] = fmaf(ai, f2.y, acc[k*8+5]);
                acc[k*8+6] = fmaf(ai, f3.x, acc[k*8+6]);
                acc[k*8+7] = fmaf(ai, f3.y, acc[k*8+7]);
            }
        }
        __syncthreads();                  // sh (b) reads done before red reuse? red != sh, but keep ordering cheap
        block_reduce_store(acc, p & 1);
        batch_barrier();
    }

    // ============ final: out = exp(s) * a_i * b_j (b from pass 4 = buf 0) ====
    combine_b(0);
    #pragma unroll 1
    for (int r8 = 0; r8 < 8; ++r8) {
        const int row = part * 128 + r8 * WPB + w;
        const size_t base = bN2 + (size_t)row * N;
        const float a = g_a[b * N + row];
        #pragma unroll
        for (int k = 0; k < 8; ++k) {
            const int j = (lane + 32 * k) * 4;
            float4 sv = *reinterpret_cast<const float4*>(s + base + j);
            float4 bv = *reinterpret_cast<const float4*>(&sh[j]);
            float4 o;
            o.x = __expf(sv.x) * (a * bv.x);
            o.y = __expf(sv.y) * (a * bv.y);
            o.z = __expf(sv.z) * (a * bv.z);
            o.w = __expf(sv.w) * (a * bv.w);
            *reinterpret_cast<float4*>(out + base + j) = o;
        }
    }
}

// ---------------------------------------------------------------------------
extern "C" void kernel_launch(void* const* d_in, const int* in_sizes, int n_in,
                              void* d_out, int out_size) {
    const float* s = (const float*)d_in[0];
    float* out = (float*)d_out;

    k_zero_bar<<<1, BATCH>>>();
    k_sinkhorn<<<dim3(BPB, BATCH), TPB>>>(s, out);
}

// round 7
// speedup vs baseline: 1.3261x; 1.3261x over previous
#include <cuda_runtime.h>
#include <cuda_bf16.h>
#include <cstdint>

// Sinkhorn, 32 x 1024 x 1024, tau=1, 10 iterations.
// Linear-domain rank-1 scaling:
//   E = exp(s); even iter: a_i = 1/sum_j E_ij b_j ; odd iter: b_j = 1/sum_i E_ij a_i
//   out = exp(s) * a_i * b_j   (fp32 exp recomputed at the end)
// Three launches:
//   k1: streaming exp+pack (bf16 E) + rowsum -> a. Flat balanced grid, high occ.
//   k2: persistent GEMV kernel, iters 1..9, 8 co-resident blocks per batch with
//       a per-batch atomic barrier; E (2 MB/batch) stays L2-resident.
//   k3: streaming final out = exp(s)*a*b. Flat balanced grid, high occ.

#define BATCH 32
#define N 1024
#define BPB 8                  // k2 blocks per batch; grid = 8 x 32 = 256
#define TPB 512
#define WPB 16

__device__ __nv_bfloat16 g_E[(size_t)BATCH * N * N];   // 64 MB
__device__ float g_a[BATCH * N];
__device__ float g_b[BATCH * N];
__device__ unsigned g_bar[BATCH * 32];

__global__ void k_zero_bar() { g_bar[threadIdx.x * 32] = 0u; }

// ===========================================================================
// k1: E = exp(s) -> bf16, a_i = 1/rowsum.  grid (128, 32) x 256 thr.
// Warp per row (8 rows/block); lane: 8 x float4 (MLP=8).
__global__ void k1_exp_rowsum(const float* __restrict__ s) {
    const int w    = threadIdx.x >> 5;
    const int lane = threadIdx.x & 31;
    const int row  = blockIdx.x * 8 + w;
    const int b    = blockIdx.y;
    const size_t base = ((size_t)b * N + row) * N;

    float sum = 0.f;
    #pragma unroll
    for (int k = 0; k < 8; ++k) {
        const int j = (lane + 32 * k) * 4;
        float4 sv = *reinterpret_cast<const float4*>(s + base + j);
        float e0 = __expf(sv.x), e1 = __expf(sv.y);
        float e2 = __expf(sv.z), e3 = __expf(sv.w);
        __nv_bfloat162 p0 = __floats2bfloat162_rn(e0, e1);
        __nv_bfloat162 p1 = __floats2bfloat162_rn(e2, e3);
        uint2 packed;
        packed.x = *reinterpret_cast<uint32_t*>(&p0);
        packed.y = *reinterpret_cast<uint32_t*>(&p1);
        *reinterpret_cast<uint2*>(&g_E[base + j]) = packed;
        sum += (e0 + e1) + (e2 + e3);
    }
    #pragma unroll
    for (int o = 16; o > 0; o >>= 1) sum += __shfl_down_sync(0xFFFFFFFFu, sum, o);
    if (lane == 0) g_a[b * N + row] = 1.0f / sum;
}

// ===========================================================================
// k2: persistent GEMV iterations 1..9 (proven R5 loop).
__global__ void __launch_bounds__(TPB, 2) k2_gemv() {
    const int part = blockIdx.x;          // 0..7
    const int b    = blockIdx.y;          // 0..31
    const int w    = threadIdx.x >> 5;    // 0..15
    const int lane = threadIdx.x & 31;
    const size_t bN2 = (size_t)b * N * N;

    __shared__ float sh[N];               // a or b staging (4 KB)
    __shared__ float red[WPB][128];       // col-pass reduction (8 KB)

    unsigned bar_target = 0;
    unsigned* const barp = &g_bar[b * 32];

    auto batch_barrier = [&]() {
        __threadfence();
        __syncthreads();
        bar_target += BPB;
        if (threadIdx.x == 0) {
            atomicAdd(barp, 1u);
            while (*(volatile unsigned*)barp < bar_target) { }
            __threadfence();
        }
        __syncthreads();
    };

    #pragma unroll 1
    for (int it = 1; it <= 9; ++it) {
        if (it & 1) {
            // ---- column pass: b_j = 1/sum_i E_ij a_i. Block owns 128 cols.
            for (int t = threadIdx.x; t < N / 4; t += TPB)
                reinterpret_cast<float4*>(sh)[t] =
                    __ldcg(&reinterpret_cast<const float4*>(&g_a[b * N])[t]);
            __syncthreads();

            const int col = part * 128 + (lane & 15) * 8;
            const int rofs = w * 2 + (lane >> 4);
            const size_t cb = bN2 + col;
            float acc[8] = {0.f, 0.f, 0.f, 0.f, 0.f, 0.f, 0.f, 0.f};
            #pragma unroll 1
            for (int it4 = 0; it4 < 8; ++it4) {
                uint4 u[4];
                float av[4];
                #pragma unroll
                for (int v = 0; v < 4; ++v) {
                    const int r = (it4 * 4 + v) * 32 + rofs;
                    u[v]  = *reinterpret_cast<const uint4*>(&g_E[cb + (size_t)r * N]);
                    av[v] = sh[r];
                }
                #pragma unroll
                for (int v = 0; v < 4; ++v) {
                    float2 f0 = __bfloat1622float2(*reinterpret_cast<__nv_bfloat162*>(&u[v].x));
                    float2 f1 = __bfloat1622float2(*reinterpret_cast<__nv_bfloat162*>(&u[v].y));
                    float2 f2 = __bfloat1622float2(*reinterpret_cast<__nv_bfloat162*>(&u[v].z));
                    float2 f3 = __bfloat1622float2(*reinterpret_cast<__nv_bfloat162*>(&u[v].w));
                    acc[0] = fmaf(av[v], f0.x, acc[0]);
                    acc[1] = fmaf(av[v], f0.y, acc[1]);
                    acc[2] = fmaf(av[v], f1.x, acc[2]);
                    acc[3] = fmaf(av[v], f1.y, acc[3]);
                    acc[4] = fmaf(av[v], f2.x, acc[4]);
                    acc[5] = fmaf(av[v], f2.y, acc[5]);
                    acc[6] = fmaf(av[v], f3.x, acc[6]);
                    acc[7] = fmaf(av[v], f3.y, acc[7]);
                }
            }
            #pragma unroll
            for (int k = 0; k < 8; ++k)
                acc[k] += __shfl_xor_sync(0xFFFFFFFFu, acc[k], 16);
            if (lane < 16) {
                #pragma unroll
                for (int k = 0; k < 8; ++k) red[w][(lane & 15) * 8 + k] = acc[k];
            }
            __syncthreads();
            if (threadIdx.x < 128) {
                float ssum = 0.f;
                #pragma unroll
                for (int ww = 0; ww < WPB; ++ww) ssum += red[ww][threadIdx.x];
                g_b[b * N + part * 128 + threadIdx.x] = 1.0f / ssum;
            }
        } else {
            // ---- row pass: a_i = 1/sum_j E_ij b_j. Warp per row, 8 rows/warp.
            for (int t = threadIdx.x; t < N / 4; t += TPB)
                reinterpret_cast<float4*>(sh)[t] =
                    __ldcg(&reinterpret_cast<const float4*>(&g_b[b * N])[t]);
            __syncthreads();

            #pragma unroll 1
            for (int rr = 0; rr < 8; ++rr) {
                const int row = part * 128 + rr * WPB + w;
                const size_t base = bN2 + (size_t)row * N;
                float sum = 0.f;
                #pragma unroll
                for (int k = 0; k < 4; ++k) {
                    const int j = lane * 8 + 256 * k;
                    uint4 u = *reinterpret_cast<const uint4*>(&g_E[base + j]);
                    float4 bv0 = *reinterpret_cast<const float4*>(sh + j);
                    float4 bv1 = *reinterpret_cast<const float4*>(sh + j + 4);
                    float2 f0 = __bfloat1622float2(*reinterpret_cast<__nv_bfloat162*>(&u.x));
                    float2 f1 = __bfloat1622float2(*reinterpret_cast<__nv_bfloat162*>(&u.y));
                    float2 f2 = __bfloat1622float2(*reinterpret_cast<__nv_bfloat162*>(&u.z));
                    float2 f3 = __bfloat1622float2(*reinterpret_cast<__nv_bfloat162*>(&u.w));
                    sum = fmaf(f0.x, bv0.x, sum); sum = fmaf(f0.y, bv0.y, sum);
                    sum = fmaf(f1.x, bv0.z, sum); sum = fmaf(f1.y, bv0.w, sum);
                    sum = fmaf(f2.x, bv1.x, sum); sum = fmaf(f2.y, bv1.y, sum);
                    sum = fmaf(f3.x, bv1.z, sum); sum = fmaf(f3.y, bv1.w, sum);
                }
                #pragma unroll
                for (int o = 16; o > 0; o >>= 1) sum += __shfl_down_sync(0xFFFFFFFFu, sum, o);
                if (lane == 0) g_a[b * N + row] = 1.0f / sum;
            }
        }
        if (it < 9) batch_barrier();
    }
}

// ===========================================================================
// k3: out = exp(s) * a_i * b_j.  grid (128, 32) x 256 thr. Warp per row.
__global__ void k3_final(const float* __restrict__ s, float* __restrict__ out) {
    __shared__ float shb[N];
    const int w    = threadIdx.x >> 5;
    const int lane = threadIdx.x & 31;
    const int row  = blockIdx.x * 8 + w;
    const int b    = blockIdx.y;
    const size_t base = ((size_t)b * N + row) * N;

    for (int t = threadIdx.x; t < N / 4; t += 256)
        reinterpret_cast<float4*>(shb)[t] =
            reinterpret_cast<const float4*>(&g_b[b * N])[t];
    __syncthreads();

    const float a = g_a[b * N + row];
    #pragma unroll
    for (int k = 0; k < 8; ++k) {
        const int j = (lane + 32 * k) * 4;
        float4 sv = *reinterpret_cast<const float4*>(s + base + j);
        float4 o;
        o.x = __expf(sv.x) * (a * shb[j]);
        o.y = __expf(sv.y) * (a * shb[j + 1]);
        o.z = __expf(sv.z) * (a * shb[j + 2]);
        o.w = __expf(sv.w) * (a * shb[j + 3]);
        *reinterpret_cast<float4*>(out + base + j) = o;
    }
}

// ---------------------------------------------------------------------------
extern "C" void kernel_launch(void* const* d_in, const int* in_sizes, int n_in,
                              void* d_out, int out_size) {
    const float* s = (const float*)d_in[0];
    float* out = (float*)d_out;

    k_zero_bar<<<1, BATCH>>>();
    k1_exp_rowsum<<<dim3(128, BATCH), 256>>>(s);
    k2_gemv<<<dim3(BPB, BATCH), TPB>>>();
    k3_final<<<dim3(128, BATCH), 256>>>(s, out);
}